// round 8
// baseline (speedup 1.0000x reference)
#include <cuda_runtime.h>
#include <cuda_fp16.h>

#define D_FEAT 64
#define MAX_NODES 100000

// Scratch (static __device__ arrays -- no allocation).
__device__ int   g_row_ptr[MAX_NODES + 1];
__device__ uint2 g_x16[MAX_NODES * 16];   // fp16 rows: 128B = 16 x uint2 per row

// Fused prep: blocks [0, rp_blocks) build row_ptr from the sorted targets;
// remaining blocks convert x (f32) -> g_x16 (fp16), 4 float4s per thread.
__global__ __launch_bounds__(256) void prep_kernel(
    const float4* __restrict__ xf4, int n_f4,
    const int* __restrict__ tgt, int n_edges, int n_nodes, int rp_blocks)
{
    if ((int)blockIdx.x < rp_blocks) {
        const int e = blockIdx.x * 256 + threadIdx.x;
        if (e >= n_edges) return;
        const int cur  = __ldg(tgt + e);
        const int prev = (e == 0) ? -1 : __ldg(tgt + e - 1);
        for (int v = prev + 1; v <= cur; ++v) g_row_ptr[v] = e;
        if (e == n_edges - 1) {
            for (int v = cur + 1; v <= n_nodes; ++v) g_row_ptr[v] = n_edges;
        }
    } else {
        const int r   = (blockIdx.x - rp_blocks) * 256 + threadIdx.x;
        const int idx = r * 4;                       // first float4 of this thread
        if (idx >= n_f4) return;
        const float4 a = __ldg(xf4 + idx + 0);
        const float4 b = __ldg(xf4 + idx + 1);
        const float4 c = __ldg(xf4 + idx + 2);
        const float4 d = __ldg(xf4 + idx + 3);
        __half2 h0 = __floats2half2_rn(a.x, a.y), h1 = __floats2half2_rn(a.z, a.w);
        __half2 h2 = __floats2half2_rn(b.x, b.y), h3 = __floats2half2_rn(b.z, b.w);
        __half2 h4 = __floats2half2_rn(c.x, c.y), h5 = __floats2half2_rn(c.z, c.w);
        __half2 h6 = __floats2half2_rn(d.x, d.y), h7 = __floats2half2_rn(d.z, d.w);
        uint4 o0, o1;
        o0.x = *reinterpret_cast<unsigned int*>(&h0);
        o0.y = *reinterpret_cast<unsigned int*>(&h1);
        o0.z = *reinterpret_cast<unsigned int*>(&h2);
        o0.w = *reinterpret_cast<unsigned int*>(&h3);
        o1.x = *reinterpret_cast<unsigned int*>(&h4);
        o1.y = *reinterpret_cast<unsigned int*>(&h5);
        o1.z = *reinterpret_cast<unsigned int*>(&h6);
        o1.w = *reinterpret_cast<unsigned int*>(&h7);
        ((uint4*)g_x16)[(size_t)r * 2 + 0] = o0;
        ((uint4*)g_x16)[(size_t)r * 2 + 1] = o1;
    }
}

__device__ __forceinline__ __half2 h2of(unsigned int u) {
    return *reinterpret_cast<__half2*>(&u);
}

// One warp per output node. Half-warp h serves edges of parity h; lane owns
// 4 features as one uint2 (4 fp16). Arithmetic core: HFMA2 into fp16
// accumulators (two parallel sets, chain depth 2) folded to f32 every 4
// edges -- replaces 4x F2F + 4x FFMA per edge with 1x F2FP + 2x HFMA2.
__global__ __launch_bounds__(128) void mp_gather_kernel(
    const float* __restrict__ ev,   // [n_edges]
    const int*   __restrict__ src,  // [n_edges]
    float*       __restrict__ out,  // [n_nodes, 64]
    int n_nodes)
{
    const int warp = (blockIdx.x * blockDim.x + threadIdx.x) >> 5;
    if (warp >= n_nodes) return;
    const int lane = threadIdx.x & 31;
    const int half = lane >> 4;
    const int hl   = lane & 15;
    const int node = warp;

    const int start = __ldg(&g_row_ptr[node]);
    const int end   = __ldg(&g_row_ptr[node + 1]);

    const uint2* __restrict__ xh = g_x16;   // row = 16 uint2
    float a0 = 0.f, a1 = 0.f, a2 = 0.f, a3 = 0.f;
    const __half2 hz = __floats2half2_rn(0.f, 0.f);

    for (int base = start; base < end; base += 32) {
        const int cnt = min(32, end - base);
        // Cooperative metadata load: lane l owns edge base+l of this batch.
        int   s_l = 0;
        float w_l = 0.f;
        if (lane < cnt) {
            s_l = __ldg(src + base + lane);
            w_l = __ldg(ev  + base + lane);
        }

        const int full = cnt >> 1;   // complete pairs (both parities valid)
        int k = 0;

        // Main path: 4 pairs per step -> 4 independent gathers per lane.
        for (; k + 4 <= full; k += 4) {
            const int j0 = 2 * (k + 0) + half;
            const int j1 = 2 * (k + 1) + half;
            const int j2 = 2 * (k + 2) + half;
            const int j3 = 2 * (k + 3) + half;
            const int s0 = __shfl_sync(0xffffffffu, s_l, j0);
            const int s1 = __shfl_sync(0xffffffffu, s_l, j1);
            const int s2 = __shfl_sync(0xffffffffu, s_l, j2);
            const int s3 = __shfl_sync(0xffffffffu, s_l, j3);
            const uint2 r0 = __ldg(&xh[(size_t)s0 * 16 + hl]);
            const uint2 r1 = __ldg(&xh[(size_t)s1 * 16 + hl]);
            const uint2 r2 = __ldg(&xh[(size_t)s2 * 16 + hl]);
            const uint2 r3 = __ldg(&xh[(size_t)s3 * 16 + hl]);
            const __half2 wh0 = __float2half2_rn(__shfl_sync(0xffffffffu, w_l, j0));
            const __half2 wh1 = __float2half2_rn(__shfl_sync(0xffffffffu, w_l, j1));
            const __half2 wh2 = __float2half2_rn(__shfl_sync(0xffffffffu, w_l, j2));
            const __half2 wh3 = __float2half2_rn(__shfl_sync(0xffffffffu, w_l, j3));
            // Two parallel fp16 accumulator sets: chain depth 2 + 1 add.
            __half2 A0 = hz, A1 = hz, B0 = hz, B1 = hz;
            A0 = __hfma2(wh0, h2of(r0.x), A0); A1 = __hfma2(wh0, h2of(r0.y), A1);
            B0 = __hfma2(wh1, h2of(r1.x), B0); B1 = __hfma2(wh1, h2of(r1.y), B1);
            A0 = __hfma2(wh2, h2of(r2.x), A0); A1 = __hfma2(wh2, h2of(r2.y), A1);
            B0 = __hfma2(wh3, h2of(r3.x), B0); B1 = __hfma2(wh3, h2of(r3.y), B1);
            const __half2 t0 = __hadd2(A0, B0);
            const __half2 t1 = __hadd2(A1, B1);
            const float2 f0 = __half22float2(t0);
            const float2 f1 = __half22float2(t1);
            a0 += f0.x; a1 += f0.y; a2 += f1.x; a3 += f1.y;
        }

        // Tail: remaining pairs (<=3) and odd edge accumulate in one short
        // fp16 chain (<=4 adds), folded once at batch end.
        __half2 T0 = hz, T1 = hz;
        for (; k < full; ++k) {
            const int j = 2 * k + half;
            const int   s = __shfl_sync(0xffffffffu, s_l, j);
            const float w = __shfl_sync(0xffffffffu, w_l, j);
            const uint2 r = __ldg(&xh[(size_t)s * 16 + hl]);
            const __half2 wh = __float2half2_rn(w);
            T0 = __hfma2(wh, h2of(r.x), T0);
            T1 = __hfma2(wh, h2of(r.y), T1);
        }
        if (cnt & 1) {
            const int j = cnt - 1;
            const int   s = __shfl_sync(0xffffffffu, s_l, j);
            float       w = __shfl_sync(0xffffffffu, w_l, j);
            if (half) w = 0.f;   // half 1 contributes zero (load still valid)
            const uint2 r = __ldg(&xh[(size_t)s * 16 + hl]);
            const __half2 wh = __float2half2_rn(w);
            T0 = __hfma2(wh, h2of(r.x), T0);
            T1 = __hfma2(wh, h2of(r.y), T1);
        }
        const float2 f0 = __half22float2(T0);
        const float2 f1 = __half22float2(T1);
        a0 += f0.x; a1 += f0.y; a2 += f1.x; a3 += f1.y;
    }

    // Combine the two half-warp partial sums (f32).
    a0 += __shfl_xor_sync(0xffffffffu, a0, 16);
    a1 += __shfl_xor_sync(0xffffffffu, a1, 16);
    a2 += __shfl_xor_sync(0xffffffffu, a2, 16);
    a3 += __shfl_xor_sync(0xffffffffu, a3, 16);

    if (half == 0) {
        float4* __restrict__ of4 = (float4*)out;
        of4[(size_t)node * 16 + hl] = make_float4(a0, a1, a2, a3);
    }
}

extern "C" void kernel_launch(void* const* d_in, const int* in_sizes, int n_in,
                              void* d_out, int out_size) {
    const float* x   = (const float*)d_in[0];
    const float* ev  = (const float*)d_in[1];
    const int*   tgt = (const int*)d_in[2];
    const int*   src = (const int*)d_in[3];
    float* out = (float*)d_out;

    const int n_edges = in_sizes[1];
    const int n_nodes = out_size / D_FEAT;
    const int n_f4    = n_nodes * (D_FEAT / 4);

    const int rp_blocks = (n_edges + 255) / 256;
    const int cv_blocks = (n_f4 / 4 + 255) / 256;
    prep_kernel<<<rp_blocks + cv_blocks, 256>>>(
        (const float4*)x, n_f4, tgt, n_edges, n_nodes, rp_blocks);

    const int threads = 128;
    const int blocks  = (n_nodes * 32 + threads - 1) / threads;
    mp_gather_kernel<<<blocks, threads>>>(ev, src, out, n_nodes);
}